// round 2
// baseline (speedup 1.0000x reference)
#include <cuda_runtime.h>

// Problem-fixed sizes (reference: N=100000, F_OUT=2). Scratch as device globals
// (no allocation allowed).
#define NMAX 100000
#define FOUT 2

__device__ __align__(16) float g_deg[NMAX];
__device__ __align__(16) float g_dis[NMAX];
__device__ __align__(16) float g_h[NMAX * FOUT];
__device__ __align__(16) float g_out[NMAX * FOUT];
__device__ float g_acc;

// ---------------------------------------------------------------------------
// K0: init deg with self-loop weight 1.0; zero the scalar accumulator.
__global__ void init_kernel(int n) {
    int i = blockIdx.x * blockDim.x + threadIdx.x;
    if (i < n) g_deg[i] = 1.0f;
    if (i == 0) g_acc = 0.0f;
}

// ---------------------------------------------------------------------------
// K1: deg[col[e]] += edge_attr[e]   (segment-sum over 3.2M edges; targets are
// 400KB -> L2-resident atomics). edge_list is int32 (JAX x64-disabled).
__global__ void deg_kernel(const int* __restrict__ col,
                           const float* __restrict__ w, int E) {
    int e = blockIdx.x * blockDim.x + threadIdx.x;
    if (e < E) {
        int c = col[e];
        atomicAdd(&g_deg[c], w[e]);
    }
}

// ---------------------------------------------------------------------------
// K2: fused  h = x @ W  (one warp per row, float4 coalesced reads of x),
//            dis = rsqrt(deg), out = h * dis^2  (self-loop contribution).
// W [512,2] row-major cached in shared memory.
__global__ void gemm_kernel(const float* __restrict__ x,
                            const float* __restrict__ W, int n, int fin) {
    __shared__ float sW[1024];  // fin * FOUT, fin <= 512
    for (int i = threadIdx.x; i < fin * FOUT; i += blockDim.x) sW[i] = W[i];
    __syncthreads();

    int warp = threadIdx.x >> 5;
    int lane = threadIdx.x & 31;
    int row = blockIdx.x * (blockDim.x >> 5) + warp;
    if (row >= n) return;

    const float4* xr = (const float4*)(x + (size_t)row * fin);
    int nq = fin >> 2;  // float4s per row (128 for fin=512)
    float a0 = 0.f, a1 = 0.f;
    for (int q = lane; q < nq; q += 32) {
        float4 v = xr[q];                 // consecutive lanes -> consecutive 16B
        int k = q << 2;
        a0 += v.x * sW[2 * k + 0] + v.y * sW[2 * k + 2] +
              v.z * sW[2 * k + 4] + v.w * sW[2 * k + 6];
        a1 += v.x * sW[2 * k + 1] + v.y * sW[2 * k + 3] +
              v.z * sW[2 * k + 5] + v.w * sW[2 * k + 7];
    }
#pragma unroll
    for (int off = 16; off; off >>= 1) {
        a0 += __shfl_down_sync(0xffffffffu, a0, off);
        a1 += __shfl_down_sync(0xffffffffu, a1, off);
    }
    if (lane == 0) {
        float d = g_deg[row];
        float dis = (d > 0.f) ? rsqrtf(d) : 0.f;
        g_dis[row] = dis;
        g_h[2 * row + 0] = a0;
        g_h[2 * row + 1] = a1;
        float s = dis * dis;  // self-loop norm (weight 1.0)
        g_out[2 * row + 0] = a0 * s;
        g_out[2 * row + 1] = a1 * s;
    }
}

// ---------------------------------------------------------------------------
// K3: edge scatter: out[col] += h[row] * (dis[row]*w*dis[col])
// Packed 8-byte float2 reduction halves RED lane count vs 2x atomicAdd.
__global__ void edge_kernel(const int* __restrict__ row,
                            const int* __restrict__ col,
                            const float* __restrict__ w, int E) {
    int e = blockIdx.x * blockDim.x + threadIdx.x;
    if (e >= E) return;
    int r = row[e];
    int c = col[e];
    float nrm = g_dis[r] * w[e] * g_dis[c];
    float2 hv = *(const float2*)(g_h + 2 * r);
    float m0 = hv.x * nrm;
    float m1 = hv.y * nrm;
    asm volatile("red.global.add.v2.f32 [%0], {%1, %2};"
                 :: "l"(g_out + 2 * c), "f"(m0), "f"(m1)
                 : "memory");
}

// ---------------------------------------------------------------------------
// K4: head: relu(out + b) dot fc_w -> block-reduced into g_acc
__global__ void head_kernel(const float* __restrict__ bvec,
                            const float* __restrict__ fcw, int n2) {
    int i = blockIdx.x * blockDim.x + threadIdx.x;
    float p = 0.f;
    if (i < n2) {
        float v = g_out[i] + bvec[i & 1];
        p = fmaxf(v, 0.f) * fcw[i];
    }
#pragma unroll
    for (int off = 16; off; off >>= 1) p += __shfl_down_sync(0xffffffffu, p, off);
    __shared__ float ws[8];
    int lane = threadIdx.x & 31, wid = threadIdx.x >> 5;
    if (lane == 0) ws[wid] = p;
    __syncthreads();
    if (wid == 0) {
        p = (lane < (blockDim.x >> 5)) ? ws[lane] : 0.f;
#pragma unroll
        for (int off = 4; off; off >>= 1) p += __shfl_down_sync(0xffffffffu, p, off);
        if (lane == 0) atomicAdd(&g_acc, p);
    }
}

// ---------------------------------------------------------------------------
// K5: sigmoid(logit + fc_b) -> d_out[0]
__global__ void final_kernel(const float* __restrict__ fcb, float* __restrict__ out) {
    float l = g_acc + fcb[0];
    out[0] = 1.f / (1.f + expf(-l));
}

// ---------------------------------------------------------------------------
extern "C" void kernel_launch(void* const* d_in, const int* in_sizes, int n_in,
                              void* d_out, int out_size) {
    const float* x   = (const float*)d_in[0];      // [N, F_IN]
    const int*   el  = (const int*)d_in[1];        // [2, E] int32 (JAX downcast)
    const float* ea  = (const float*)d_in[2];      // [E]
    const float* W   = (const float*)d_in[3];      // [F_IN, 2]
    const float* b   = (const float*)d_in[4];      // [2]
    const float* fcw = (const float*)d_in[5];      // [2N]
    const float* fcb = (const float*)d_in[6];      // scalar

    int E  = in_sizes[2];
    int n2 = in_sizes[5];
    int n  = n2 / FOUT;
    int fin = in_sizes[0] / n;

    const int* rowp = el;
    const int* colp = el + E;

    init_kernel<<<(n + 255) / 256, 256>>>(n);
    deg_kernel<<<(E + 255) / 256, 256>>>(colp, ea, E);
    // 8 warps/block -> 8 rows/block
    gemm_kernel<<<(n + 7) / 8, 256>>>(x, W, n, fin);
    edge_kernel<<<(E + 255) / 256, 256>>>(rowp, colp, ea, E);
    head_kernel<<<(n2 + 255) / 256, 256>>>(b, fcw, n2);
    final_kernel<<<1, 1>>>(fcb, (float*)d_out);
}

// round 3
// speedup vs baseline: 1.1657x; 1.1657x over previous
#include <cuda_runtime.h>

// Problem-fixed sizes (reference: N=100000, F_OUT=2). Scratch as device globals.
#define NMAX 100000
#define FOUT 2

__device__ __align__(16) float g_deg[NMAX];
__device__ __align__(16) float g_dis[NMAX];
__device__ __align__(16) float g_h[NMAX * FOUT];    // raw x@W
__device__ __align__(16) float g_hs[NMAX * FOUT];   // h * dis  (gather source)
__device__ __align__(16) float g_acc[NMAX * FOUT];  // Σ hs[row]*w  (+ self-loop hs[c])
__device__ float g_acc_scalar;

// ---------------------------------------------------------------------------
// K0: deg starts at self-loop weight 1.0; zero the scalar accumulator.
__global__ void init_kernel(int n) {
    int i = blockIdx.x * blockDim.x + threadIdx.x;
    if (i < n) g_deg[i] = 1.0f;
    if (i == 0) g_acc_scalar = 0.0f;
}

// ---------------------------------------------------------------------------
// K1 (fused): blocks [0, degB) stream col/w and do deg atomics (L2-bound);
// blocks [degB, degB+gemmB) compute h = x @ W (DRAM-bound). The two block
// families use disjoint pipes and overlap inside one launch.
__global__ void fused_deg_gemm(const int* __restrict__ col,
                               const float* __restrict__ w, int E, int degB,
                               const float* __restrict__ x,
                               const float* __restrict__ W, int n, int fin) {
    if ((int)blockIdx.x < degB) {
        // --- deg atomics: 4 edges per thread, vectorized streams ---
        int t = blockIdx.x * blockDim.x + threadIdx.x;
        int base = t * 4;
        if (base + 3 < E) {
            int4 c4 = *(const int4*)(col + base);
            float4 w4 = *(const float4*)(w + base);
            atomicAdd(&g_deg[c4.x], w4.x);
            atomicAdd(&g_deg[c4.y], w4.y);
            atomicAdd(&g_deg[c4.z], w4.z);
            atomicAdd(&g_deg[c4.w], w4.w);
        } else {
            for (int e = base; e < E; ++e) atomicAdd(&g_deg[col[e]], w[e]);
        }
        return;
    }
    // --- GEMM: one warp per row, float4 coalesced reads of x ---
    __shared__ float sW[1024];  // fin * FOUT, fin <= 512
    for (int i = threadIdx.x; i < fin * FOUT; i += blockDim.x) sW[i] = W[i];
    __syncthreads();

    int warp = threadIdx.x >> 5;
    int lane = threadIdx.x & 31;
    int row = ((int)blockIdx.x - degB) * (blockDim.x >> 5) + warp;
    if (row >= n) return;

    const float4* xr = (const float4*)(x + (size_t)row * fin);
    int nq = fin >> 2;
    float a0 = 0.f, a1 = 0.f;
    for (int q = lane; q < nq; q += 32) {
        float4 v = xr[q];
        int k = q << 2;
        a0 += v.x * sW[2 * k + 0] + v.y * sW[2 * k + 2] +
              v.z * sW[2 * k + 4] + v.w * sW[2 * k + 6];
        a1 += v.x * sW[2 * k + 1] + v.y * sW[2 * k + 3] +
              v.z * sW[2 * k + 5] + v.w * sW[2 * k + 7];
    }
#pragma unroll
    for (int off = 16; off; off >>= 1) {
        a0 += __shfl_down_sync(0xffffffffu, a0, off);
        a1 += __shfl_down_sync(0xffffffffu, a1, off);
    }
    if (lane == 0) {
        g_h[2 * row + 0] = a0;
        g_h[2 * row + 1] = a1;
    }
}

// ---------------------------------------------------------------------------
// K2: dis = rsqrt(deg); hs = h*dis; acc = hs (self-loop term, weight 1).
__global__ void post_kernel(int n) {
    int i = blockIdx.x * blockDim.x + threadIdx.x;
    if (i >= n) return;
    float d = g_deg[i];
    float dis = (d > 0.f) ? rsqrtf(d) : 0.f;
    g_dis[i] = dis;
    float2 h = *(const float2*)(g_h + 2 * i);
    float2 hs = make_float2(h.x * dis, h.y * dis);
    *(float2*)(g_hs + 2 * i) = hs;
    *(float2*)(g_acc + 2 * i) = hs;
}

// ---------------------------------------------------------------------------
// K3: edge scatter: acc[col] += hs[row] * w.  ONE random gather sector per
// edge (hs float2) + one v2 RED. 4 edges/thread for ILP on the gathers.
__global__ void edge_kernel(const int* __restrict__ row,
                            const int* __restrict__ col,
                            const float* __restrict__ w, int E) {
    int t = blockIdx.x * blockDim.x + threadIdx.x;
    int base = t * 4;
    if (base + 3 < E) {
        int4 r4 = *(const int4*)(row + base);
        int4 c4 = *(const int4*)(col + base);
        float4 w4 = *(const float4*)(w + base);
        float2 h0 = __ldg((const float2*)(g_hs + 2 * r4.x));
        float2 h1 = __ldg((const float2*)(g_hs + 2 * r4.y));
        float2 h2 = __ldg((const float2*)(g_hs + 2 * r4.z));
        float2 h3 = __ldg((const float2*)(g_hs + 2 * r4.w));
        asm volatile("red.global.add.v2.f32 [%0], {%1, %2};" ::
                     "l"(g_acc + 2 * c4.x), "f"(h0.x * w4.x), "f"(h0.y * w4.x) : "memory");
        asm volatile("red.global.add.v2.f32 [%0], {%1, %2};" ::
                     "l"(g_acc + 2 * c4.y), "f"(h1.x * w4.y), "f"(h1.y * w4.y) : "memory");
        asm volatile("red.global.add.v2.f32 [%0], {%1, %2};" ::
                     "l"(g_acc + 2 * c4.z), "f"(h2.x * w4.z), "f"(h2.y * w4.z) : "memory");
        asm volatile("red.global.add.v2.f32 [%0], {%1, %2};" ::
                     "l"(g_acc + 2 * c4.w), "f"(h3.x * w4.w), "f"(h3.y * w4.w) : "memory");
    } else {
        for (int e = base; e < E; ++e) {
            int r = row[e], c = col[e];
            float ww = w[e];
            float2 hv = __ldg((const float2*)(g_hs + 2 * r));
            asm volatile("red.global.add.v2.f32 [%0], {%1, %2};" ::
                         "l"(g_acc + 2 * c), "f"(hv.x * ww), "f"(hv.y * ww) : "memory");
        }
    }
}

// ---------------------------------------------------------------------------
// K4: head: out = relu(dis[c]*acc + b); partial = out · fc_w -> g_acc_scalar.
// One thread per node (both output channels).
__global__ void head_kernel(const float* __restrict__ bvec,
                            const float* __restrict__ fcw, int n) {
    int i = blockIdx.x * blockDim.x + threadIdx.x;
    float p = 0.f;
    if (i < n) {
        float dis = g_dis[i];
        float2 a = *(const float2*)(g_acc + 2 * i);
        float2 fw = *(const float2*)(fcw + 2 * i);
        float v0 = fmaxf(dis * a.x + bvec[0], 0.f);
        float v1 = fmaxf(dis * a.y + bvec[1], 0.f);
        p = v0 * fw.x + v1 * fw.y;
    }
#pragma unroll
    for (int off = 16; off; off >>= 1) p += __shfl_down_sync(0xffffffffu, p, off);
    __shared__ float ws[8];
    int lane = threadIdx.x & 31, wid = threadIdx.x >> 5;
    if (lane == 0) ws[wid] = p;
    __syncthreads();
    if (wid == 0) {
        p = (lane < (blockDim.x >> 5)) ? ws[lane] : 0.f;
#pragma unroll
        for (int off = 4; off; off >>= 1) p += __shfl_down_sync(0xffffffffu, p, off);
        if (lane == 0) atomicAdd(&g_acc_scalar, p);
    }
}

// ---------------------------------------------------------------------------
// K5: sigmoid(logit + fc_b) -> d_out[0]
__global__ void final_kernel(const float* __restrict__ fcb, float* __restrict__ out) {
    float l = g_acc_scalar + fcb[0];
    out[0] = 1.f / (1.f + expf(-l));
}

// ---------------------------------------------------------------------------
extern "C" void kernel_launch(void* const* d_in, const int* in_sizes, int n_in,
                              void* d_out, int out_size) {
    const float* x   = (const float*)d_in[0];      // [N, F_IN]
    const int*   el  = (const int*)d_in[1];        // [2, E] int32 (JAX downcast)
    const float* ea  = (const float*)d_in[2];      // [E]
    const float* W   = (const float*)d_in[3];      // [F_IN, 2]
    const float* b   = (const float*)d_in[4];      // [2]
    const float* fcw = (const float*)d_in[5];      // [2N]
    const float* fcb = (const float*)d_in[6];      // scalar

    int E  = in_sizes[2];
    int n2 = in_sizes[5];
    int n  = n2 / FOUT;
    int fin = in_sizes[0] / n;

    const int* rowp = el;
    const int* colp = el + E;

    // deg blocks: 256 thr * 4 edges = 1024 edges/block
    int degB  = (E + 1023) / 1024;
    int gemmB = (n + 7) / 8;  // 8 warps -> 8 rows per block

    init_kernel<<<(n + 255) / 256, 256>>>(n);
    fused_deg_gemm<<<degB + gemmB, 256>>>(colp, ea, E, degB, x, W, n, fin);
    post_kernel<<<(n + 255) / 256, 256>>>(n);
    edge_kernel<<<(E / 4 + 255) / 256, 256>>>(rowp, colp, ea, E);
    head_kernel<<<(n + 255) / 256, 256>>>(b, fcw, n);
    final_kernel<<<1, 1>>>(fcb, (float*)d_out);
}

// round 4
// speedup vs baseline: 1.1862x; 1.0175x over previous
#include <cuda_runtime.h>

// Problem-fixed sizes (reference: N=100000, F_IN=512, F_OUT=2).
#define NMAX 100000
#define FOUT 2
#define FIN 512

__device__ __align__(16) float g_deg[NMAX];
__device__ __align__(16) float g_dis[NMAX];
__device__ __align__(16) float g_h[NMAX * FOUT];    // raw x@W
__device__ __align__(16) float g_hs[NMAX * FOUT];   // h * dis (gather source)
__device__ __align__(16) float g_acc[NMAX * FOUT];  // self-loop + edge sums
__device__ float g_acc_scalar;
__device__ unsigned int g_ticket;

// ---------------------------------------------------------------------------
// K0: deg starts at self-loop weight 1.0; zero scalar accumulator + ticket.
__global__ void init_kernel(int n) {
    int i = blockIdx.x * blockDim.x + threadIdx.x;
    if (i < n) g_deg[i] = 1.0f;
    if (i == 0) { g_acc_scalar = 0.0f; g_ticket = 0u; }
}

// ---------------------------------------------------------------------------
// K1 (fused): blocks [0, gemmB) compute h = x @ W (DRAM-streaming, launched
// first so wave 1 starts pulling HBM); blocks [gemmB, gemmB+degB) do the
// deg segment-sum atomics (L2 pipe) and overlap.
__global__ __launch_bounds__(256) void fused_gemm_deg(
        const float* __restrict__ x, const float* __restrict__ W, int n,
        int gemmB, const int* __restrict__ col, const float* __restrict__ w,
        int E) {
    if ((int)blockIdx.x >= gemmB) {
        // --- deg atomics: 4 edges/thread, vectorized streams ---
        int t = ((int)blockIdx.x - gemmB) * blockDim.x + threadIdx.x;
        int base = t * 4;
        if (base + 3 < E) {
            int4 c4 = *(const int4*)(col + base);
            float4 w4 = *(const float4*)(w + base);
            atomicAdd(&g_deg[c4.x], w4.x);
            atomicAdd(&g_deg[c4.y], w4.y);
            atomicAdd(&g_deg[c4.z], w4.z);
            atomicAdd(&g_deg[c4.w], w4.w);
        } else {
            for (int e = base; e < E; ++e) atomicAdd(&g_deg[col[e]], w[e]);
        }
        return;
    }
    // --- GEMM: one warp per row; 4 independent LDG.128 cover the 2KB row ---
    __shared__ __align__(16) float sW[FIN * FOUT];
    for (int i = threadIdx.x; i < FIN * FOUT; i += blockDim.x) sW[i] = W[i];
    __syncthreads();

    int warp = threadIdx.x >> 5;
    int lane = threadIdx.x & 31;
    int row = (int)blockIdx.x * (blockDim.x >> 5) + warp;
    if (row >= n) return;

    const float4* xr = (const float4*)(x + (size_t)row * FIN);
    const float4* sW4 = (const float4*)sW;

    // independent loads -> MLP 4 per warp
    float4 v0 = xr[lane];
    float4 v1 = xr[lane + 32];
    float4 v2 = xr[lane + 64];
    float4 v3 = xr[lane + 96];

    float a0 = 0.f, a1 = 0.f;
#define ACCUM(v, q)                                                        \
    {                                                                      \
        float4 wa = sW4[2 * (q)];                                          \
        float4 wb = sW4[2 * (q) + 1];                                      \
        a0 += v.x * wa.x + v.y * wa.z + v.z * wb.x + v.w * wb.z;           \
        a1 += v.x * wa.y + v.y * wa.w + v.z * wb.y + v.w * wb.w;           \
    }
    ACCUM(v0, lane)
    ACCUM(v1, lane + 32)
    ACCUM(v2, lane + 64)
    ACCUM(v3, lane + 96)
#undef ACCUM

#pragma unroll
    for (int off = 16; off; off >>= 1) {
        a0 += __shfl_down_sync(0xffffffffu, a0, off);
        a1 += __shfl_down_sync(0xffffffffu, a1, off);
    }
    if (lane == 0) {
        g_h[2 * row + 0] = a0;
        g_h[2 * row + 1] = a1;
    }
}

// ---------------------------------------------------------------------------
// K2: dis = rsqrt(deg); hs = h*dis; acc = hs (self-loop, weight 1).
__global__ void post_kernel(int n) {
    int i = blockIdx.x * blockDim.x + threadIdx.x;
    if (i >= n) return;
    float d = g_deg[i];
    float dis = (d > 0.f) ? rsqrtf(d) : 0.f;
    g_dis[i] = dis;
    float2 h = *(const float2*)(g_h + 2 * i);
    float2 hs = make_float2(h.x * dis, h.y * dis);
    *(float2*)(g_hs + 2 * i) = hs;
    *(float2*)(g_acc + 2 * i) = hs;
}

// ---------------------------------------------------------------------------
// K3: edge scatter: acc[col] += hs[row] * w. One random 8B gather + one v2
// RED per edge; 4 edges/thread for gather ILP.
__global__ __launch_bounds__(256) void edge_kernel(
        const int* __restrict__ row, const int* __restrict__ col,
        const float* __restrict__ w, int E) {
    int t = blockIdx.x * blockDim.x + threadIdx.x;
    int base = t * 4;
    if (base + 3 < E) {
        int4 r4 = *(const int4*)(row + base);
        int4 c4 = *(const int4*)(col + base);
        float4 w4 = *(const float4*)(w + base);
        float2 h0 = __ldg((const float2*)(g_hs + 2 * r4.x));
        float2 h1 = __ldg((const float2*)(g_hs + 2 * r4.y));
        float2 h2 = __ldg((const float2*)(g_hs + 2 * r4.z));
        float2 h3 = __ldg((const float2*)(g_hs + 2 * r4.w));
        asm volatile("red.global.add.v2.f32 [%0], {%1, %2};" ::
                     "l"(g_acc + 2 * c4.x), "f"(h0.x * w4.x), "f"(h0.y * w4.x) : "memory");
        asm volatile("red.global.add.v2.f32 [%0], {%1, %2};" ::
                     "l"(g_acc + 2 * c4.y), "f"(h1.x * w4.y), "f"(h1.y * w4.y) : "memory");
        asm volatile("red.global.add.v2.f32 [%0], {%1, %2};" ::
                     "l"(g_acc + 2 * c4.z), "f"(h2.x * w4.z), "f"(h2.y * w4.z) : "memory");
        asm volatile("red.global.add.v2.f32 [%0], {%1, %2};" ::
                     "l"(g_acc + 2 * c4.w), "f"(h3.x * w4.w), "f"(h3.y * w4.w) : "memory");
    } else {
        for (int e = base; e < E; ++e) {
            int r = row[e], c = col[e];
            float ww = w[e];
            float2 hv = __ldg((const float2*)(g_hs + 2 * r));
            asm volatile("red.global.add.v2.f32 [%0], {%1, %2};" ::
                         "l"(g_acc + 2 * c), "f"(hv.x * ww), "f"(hv.y * ww) : "memory");
        }
    }
}

// ---------------------------------------------------------------------------
// K4: head (+ fused final): relu(dis*acc + b) · fc_w -> g_acc_scalar;
// last block through the ticket applies sigmoid into d_out.
__global__ void head_kernel(const float* __restrict__ bvec,
                            const float* __restrict__ fcw,
                            const float* __restrict__ fcb,
                            float* __restrict__ out, int n, int nblocks) {
    int i = blockIdx.x * blockDim.x + threadIdx.x;
    float p = 0.f;
    if (i < n) {
        float dis = g_dis[i];
        float2 a = *(const float2*)(g_acc + 2 * i);
        float2 fw = *(const float2*)(fcw + 2 * i);
        float v0 = fmaxf(dis * a.x + bvec[0], 0.f);
        float v1 = fmaxf(dis * a.y + bvec[1], 0.f);
        p = v0 * fw.x + v1 * fw.y;
    }
#pragma unroll
    for (int off = 16; off; off >>= 1) p += __shfl_down_sync(0xffffffffu, p, off);
    __shared__ float ws[8];
    __shared__ bool is_last;
    int lane = threadIdx.x & 31, wid = threadIdx.x >> 5;
    if (lane == 0) ws[wid] = p;
    __syncthreads();
    if (wid == 0) {
        p = (lane < (blockDim.x >> 5)) ? ws[lane] : 0.f;
#pragma unroll
        for (int off = 4; off; off >>= 1) p += __shfl_down_sync(0xffffffffu, p, off);
        if (lane == 0) {
            atomicAdd(&g_acc_scalar, p);
            __threadfence();
            unsigned int t = atomicAdd(&g_ticket, 1u);
            is_last = (t == (unsigned int)(nblocks - 1));
        }
    }
    __syncthreads();
    if (is_last && threadIdx.x == 0) {
        float l = g_acc_scalar + fcb[0];
        out[0] = 1.f / (1.f + expf(-l));
    }
}

// ---------------------------------------------------------------------------
extern "C" void kernel_launch(void* const* d_in, const int* in_sizes, int n_in,
                              void* d_out, int out_size) {
    const float* x   = (const float*)d_in[0];      // [N, F_IN]
    const int*   el  = (const int*)d_in[1];        // [2, E] int32 (JAX downcast)
    const float* ea  = (const float*)d_in[2];      // [E]
    const float* W   = (const float*)d_in[3];      // [F_IN, 2]
    const float* b   = (const float*)d_in[4];      // [2]
    const float* fcw = (const float*)d_in[5];      // [2N]
    const float* fcb = (const float*)d_in[6];      // scalar

    int E  = in_sizes[2];
    int n2 = in_sizes[5];
    int n  = n2 / FOUT;

    const int* rowp = el;
    const int* colp = el + E;

    int gemmB = (n + 7) / 8;          // 8 warps -> 8 rows per block
    int degB  = (E + 1023) / 1024;    // 256 thr * 4 edges per block
    int headB = (n + 255) / 256;

    init_kernel<<<(n + 255) / 256, 256>>>(n);
    fused_gemm_deg<<<gemmB + degB, 256>>>(x, W, n, gemmB, colp, ea, E);
    post_kernel<<<(n + 255) / 256, 256>>>(n);
    edge_kernel<<<(E / 4 + 255) / 256, 256>>>(rowp, colp, ea, E);
    head_kernel<<<headB, 256>>>(b, fcw, fcb, (float*)d_out, n, headB);
}